// round 6
// baseline (speedup 1.0000x reference)
#include <cuda_runtime.h>
#include <cstdint>

// Rotated ROI cropper v6: cp.async staging, fixed 40x40 guard window.
//   x:     [8, 3, 1024, 1024] fp32
//   boxes: [8, 64, 5] fp32  (cx, cy, w, h, angle_deg)
//   out:   [512, 3, 48, 320] fp32
//
// Block = one 32x16 output tile of one box (2 rows/thread, 256 threads).
// Source bbox of a 32x16 tile is <= 35 px/side (bw<=300, bh<=60, |ang|<=45);
// with 1-px guard + tap the 40x40 window always covers it. The window is
// staged unconditionally with cp.async (zero-fill outside the image via
// src-size=0), split planes: float2 (c0,c1) + float c2.

#define IMG_H 1024
#define IMG_W 1024
#define OUT_H 48
#define OUT_W 320
#define CHANS 3
#define N_BOXES_TOTAL 512
#define PLANE (IMG_H * IMG_W)
#define OPLANE (OUT_H * OUT_W)

#define TILE_OX 32
#define TILE_OY 16
#define NTX (OUT_W / TILE_OX)   // 10
#define NTY (OUT_H / TILE_OY)   // 3

#define STILE  40
#define SPITCH 41
#define IDX_LIM ((STILE - 2) * SPITCH + (STILE - 2))   // 1596

#define NTHREADS 256

__device__ __forceinline__ void cp4(uint32_t dst, const float* src, uint32_t sz) {
    asm volatile("cp.async.ca.shared.global [%0], [%1], 4, %2;\n"
                 :: "r"(dst), "l"(src), "r"(sz) : "memory");
}

__global__ __launch_bounds__(NTHREADS, 8)
void rotated_roi_crop_v6(const float* __restrict__ x,
                         const float* __restrict__ boxes,
                         float* __restrict__ out) {
    __shared__ float2 tileAB[STILE][SPITCH];  // (c0, c1)
    __shared__ float  tileC [STILE][SPITCH];  // c2
    __shared__ float  dump[4];                // sink for inactive staging lanes

    const int bid     = blockIdx.x;
    const int tx_tile = bid % NTX;
    const int ty_tile = (bid / NTX) % NTY;
    const int g       = bid / (NTX * NTY);

    // ---- box params (uniform broadcast) ----
    const float* bp = boxes + g * 5;
    const float cx  = bp[0];
    const float cy  = bp[1];
    const float bw  = bp[2];
    const float bh  = bp[3];
    const float ang = bp[4];

    const float theta = -ang * 0.017453292519943295f;
    float s_, c_;
    sincosf(theta, &s_, &c_);
    const float b = c_ * 0.5f;
    const float a = s_ * 0.5f;

    const float p0x = cx - a * bh - b * bw;
    const float p0y = cy + b * bh - a * bw;
    const float p1x = cx + a * bh - b * bw;
    const float p1y = cy - b * bh - a * bw;
    const float p2x = 2.0f * cx - p0x;
    const float p2y = 2.0f * cy - p0y;

    const float ex_x = p2x - p1x;   // source delta per unit u
    const float ex_y = p2y - p1y;
    const float ey_x = p0x - p1x;   // source delta per unit v
    const float ey_y = p0y - p1y;

    // ---- source bbox corners of this output tile ----
    const float u0 = (float)(tx_tile * TILE_OX)               * (1.0f / OUT_W);
    const float u1 = (float)(tx_tile * TILE_OX + TILE_OX - 1) * (1.0f / OUT_W);
    const float v0 = (float)(ty_tile * TILE_OY)               * (1.0f / OUT_H);
    const float v1 = (float)(ty_tile * TILE_OY + TILE_OY - 1) * (1.0f / OUT_H);

    const float sxa = p1x + u0 * ex_x + v0 * ey_x;
    const float sxb = p1x + u1 * ex_x + v0 * ey_x;
    const float sxc = p1x + u0 * ex_x + v1 * ey_x;
    const float sxd = p1x + u1 * ex_x + v1 * ey_x;
    const float sya = p1y + u0 * ex_y + v0 * ey_y;
    const float syb = p1y + u1 * ex_y + v0 * ey_y;
    const float syc = p1y + u0 * ex_y + v1 * ey_y;
    const float syd = p1y + u1 * ex_y + v1 * ey_y;

    const int x_org = (int)floorf(fminf(fminf(sxa, sxb), fminf(sxc, sxd))) - 1;  // 1-px guard
    const int y_org = (int)floorf(fminf(fminf(sya, syb), fminf(syc, syd))) - 1;

    const int lane = threadIdx.x & 31;
    const int wrp  = threadIdx.x >> 5;   // 0..7

    // ---- staging: full 40x40 window via cp.async, zero-filled outside image ----
    const int batch = g >> 6;
    const float* img = x + (size_t)batch * CHANS * PLANE;

    const uint32_t ab_base  = (uint32_t)__cvta_generic_to_shared(&tileAB[0][0]);
    const uint32_t c_base   = (uint32_t)__cvta_generic_to_shared(&tileC[0][0]);
    const uint32_t dump_u32 = (uint32_t)__cvta_generic_to_shared(&dump[0]);

    const bool seg1_live = (lane < (STILE - 32));   // lanes 0..7 handle cols 32..39

#pragma unroll
    for (int k = 0; k < 5; k++) {
        const int yy = wrp + k * 8;                // 0..39
        const int gy = y_org + yy;
        const bool rok = ((unsigned)gy < IMG_H);
        const int gyc = min(max(gy, 0), IMG_H - 1);
        const float* rp = img + (size_t)gyc * IMG_W;

        // seg0: cols 0..31
        {
            const int xx = lane;
            const int gx = x_org + xx;
            const bool ok = rok & ((unsigned)gx < IMG_W);
            const int gxc = min(max(gx, 0), IMG_W - 1);
            const uint32_t sz = ok ? 4u : 0u;
            const uint32_t dAB = ab_base + (uint32_t)(yy * SPITCH + xx) * 8u;
            const uint32_t dC  = c_base  + (uint32_t)(yy * SPITCH + xx) * 4u;
            cp4(dAB,     rp + gxc,             sz);
            cp4(dAB + 4, rp + gxc + PLANE,     sz);
            cp4(dC,      rp + gxc + 2 * PLANE, sz);
        }
        // seg1: cols 32..39 (lanes 0..7); others write zeros to dump
        {
            const int xx = 32 + lane;
            const int gx = x_org + xx;
            const bool ok = seg1_live & rok & ((unsigned)gx < IMG_W);
            const int gxc = min(max(gx, 0), IMG_W - 1);
            const uint32_t sz = ok ? 4u : 0u;
            const uint32_t off = (uint32_t)(yy * SPITCH + xx);
            const uint32_t dAB = seg1_live ? (ab_base + off * 8u) : dump_u32;
            const uint32_t dC  = seg1_live ? (c_base  + off * 4u) : dump_u32;
            cp4(dAB,     rp + gxc,             sz);
            cp4(dAB + 4, rp + gxc + PLANE,     sz);
            cp4(dC,      rp + gxc + 2 * PLANE, sz);
        }
    }
    asm volatile("cp.async.commit_group;\n" ::: "memory");
    asm volatile("cp.async.wait_group 0;\n" ::: "memory");
    __syncthreads();

    // ---- compute: warp = 32 contiguous output px; 2 rows per thread ----
    const int ox  = tx_tile * TILE_OX + lane;
    const int oy0 = ty_tile * TILE_OY + wrp * 2;

    const float u  = (float)ox  * (1.0f / OUT_W);
    const float vb = (float)oy0 * (1.0f / OUT_H);

    float sx = fmaf(vb, ey_x, fmaf(u, ex_x, p1x)) - (float)x_org;
    float sy = fmaf(vb, ey_y, fmaf(u, ex_y, p1y)) - (float)y_org;
    const float dvx = ey_x * (1.0f / OUT_H);
    const float dvy = ey_y * (1.0f / OUT_H);

    const float2* __restrict__ tAB = &tileAB[0][0];
    const float*  __restrict__ tC  = &tileC[0][0];

    float* ob = out + (((size_t)g * CHANS) * OUT_H + oy0) * OUT_W + ox;

#pragma unroll
    for (int r = 0; r < 2; r++) {
        const float x0f = floorf(sx);
        const float y0f = floorf(sy);
        const float dx = sx - x0f;
        const float dy = sy - y0f;

        int idx = (int)y0f * SPITCH + (int)x0f;
        idx = min(max(idx, 0), IDX_LIM);   // memory safety only; never binds in-spec

        const float omdx = 1.0f - dx;
        const float omdy = 1.0f - dy;
        const float w00 = omdx * omdy;
        const float w10 = dx * omdy;
        const float w01 = omdx * dy;
        const float w11 = dx * dy;

        const float2 t00 = tAB[idx];
        const float2 t10 = tAB[idx + 1];
        const float2 t01 = tAB[idx + SPITCH];
        const float2 t11 = tAB[idx + SPITCH + 1];
        const float  c00 = tC[idx];
        const float  c10 = tC[idx + 1];
        const float  c01 = tC[idx + SPITCH];
        const float  c11 = tC[idx + SPITCH + 1];

        const float r0 = fmaf(t11.x, w11, fmaf(t01.x, w01, fmaf(t10.x, w10, t00.x * w00)));
        const float r1 = fmaf(t11.y, w11, fmaf(t01.y, w01, fmaf(t10.y, w10, t00.y * w00)));
        const float r2 = fmaf(c11,   w11, fmaf(c01,   w01, fmaf(c10,   w10, c00   * w00)));

        ob[0]          = r0;
        ob[OPLANE]     = r1;
        ob[2 * OPLANE] = r2;

        sx += dvx;
        sy += dvy;
        ob += OUT_W;
    }
}

extern "C" void kernel_launch(void* const* d_in, const int* in_sizes, int n_in,
                              void* d_out, int out_size) {
    const float* x     = (const float*)d_in[0];
    const float* boxes = (const float*)d_in[1];
    float* out         = (float*)d_out;

    dim3 grid(N_BOXES_TOTAL * NTX * NTY);   // 15360
    dim3 block(NTHREADS);
    rotated_roi_crop_v6<<<grid, block>>>(x, boxes, out);
}

// round 7
// speedup vs baseline: 3.1773x; 3.1773x over previous
#include <cuda_runtime.h>

// Rotated ROI cropper v7: R4 structure + batched (MLP) staging + lean compute.
//   x:     [8, 3, 1024, 1024] fp32
//   boxes: [8, 64, 5] fp32  (cx, cy, w, h, angle_deg)
//   out:   [512, 3, 48, 320] fp32
//
// Block = one 32x16 output tile of one box (2 rows/thread, 256 threads).
// Source window of a 32x16 tile is <= 38 px/side (bw<=300, bh<=60, |ang|<=45,
// span <= sqrt(29.06^2+18.75^2)+2 = 36.6). Fixed 38x38 window staged via
// linear thread->cell map in two load-all/store-all batches (high MLP, two
// scoreboard stalls per warp instead of five). Split smem planes:
// float2 (c0,c1) + float c2. Guard border kills per-pixel clamps.

#define IMG_H 1024
#define IMG_W 1024
#define OUT_H 48
#define OUT_W 320
#define CHANS 3
#define N_BOXES_TOTAL 512
#define PLANE (IMG_H * IMG_W)
#define OPLANE (OUT_H * OUT_W)

#define TILE_OX 32
#define TILE_OY 16
#define NTX (OUT_W / TILE_OX)   // 10
#define NTY (OUT_H / TILE_OY)   // 3

#define STILE  38
#define SPITCH 39
#define CELLS  (STILE * STILE)                          // 1444
#define IDX_LIM ((STILE - 2) * SPITCH + (STILE - 2))    // 1440

#define NTHREADS 256

__global__ __launch_bounds__(NTHREADS, 6)
void rotated_roi_crop_v7(const float* __restrict__ x,
                         const float* __restrict__ boxes,
                         float* __restrict__ out) {
    __shared__ float2 tileAB[STILE][SPITCH];  // (c0, c1)
    __shared__ float  tileC [STILE][SPITCH];  // c2

    const int bid     = blockIdx.x;
    const int tx_tile = bid % NTX;
    const int ty_tile = (bid / NTX) % NTY;
    const int g       = bid / (NTX * NTY);

    // ---- box params (uniform broadcast) ----
    const float* bp = boxes + g * 5;
    const float cx  = bp[0];
    const float cy  = bp[1];
    const float bw  = bp[2];
    const float bh  = bp[3];
    const float ang = bp[4];

    const float theta = -ang * 0.017453292519943295f;
    float s_, c_;
    sincosf(theta, &s_, &c_);
    const float b = c_ * 0.5f;
    const float a = s_ * 0.5f;

    const float p0x = cx - a * bh - b * bw;
    const float p0y = cy + b * bh - a * bw;
    const float p1x = cx + a * bh - b * bw;
    const float p1y = cy - b * bh - a * bw;
    const float p2x = 2.0f * cx - p0x;
    const float p2y = 2.0f * cy - p0y;

    const float ex_x = p2x - p1x;   // source delta per unit u
    const float ex_y = p2y - p1y;
    const float ey_x = p0x - p1x;   // source delta per unit v
    const float ey_y = p0y - p1y;

    // ---- source bbox corners of this output tile ----
    const float u0 = (float)(tx_tile * TILE_OX)               * (1.0f / OUT_W);
    const float u1 = (float)(tx_tile * TILE_OX + TILE_OX - 1) * (1.0f / OUT_W);
    const float v0 = (float)(ty_tile * TILE_OY)               * (1.0f / OUT_H);
    const float v1 = (float)(ty_tile * TILE_OY + TILE_OY - 1) * (1.0f / OUT_H);

    const float sxa = p1x + u0 * ex_x + v0 * ey_x;
    const float sxb = p1x + u1 * ex_x + v0 * ey_x;
    const float sxc = p1x + u0 * ex_x + v1 * ey_x;
    const float sxd = p1x + u1 * ex_x + v1 * ey_x;
    const float sya = p1y + u0 * ex_y + v0 * ey_y;
    const float syb = p1y + u1 * ex_y + v0 * ey_y;
    const float syc = p1y + u0 * ex_y + v1 * ey_y;
    const float syd = p1y + u1 * ex_y + v1 * ey_y;

    const int x_org = (int)floorf(fminf(fminf(sxa, sxb), fminf(sxc, sxd))) - 1;  // 1-px guard
    const int y_org = (int)floorf(fminf(fminf(sya, syb), fminf(syc, syd))) - 1;

    // ---- staging: fixed 38x38 window, linear map, 2 batches of 3 cells ----
    const int batch = g >> 6;
    const float* img = x + (size_t)batch * CHANS * PLANE;
    const int tid = threadIdx.x;

#pragma unroll
    for (int half = 0; half < 2; half++) {
        float vc0[3], vc1[3], vc2[3];
        int   soff[3];
        bool  live[3];
#pragma unroll
        for (int j = 0; j < 3; j++) {
            const int idx = tid + (half * 3 + j) * NTHREADS;
            const unsigned yy = (unsigned)idx / STILE;
            const unsigned xx = (unsigned)idx - yy * STILE;
            const bool in = (idx < CELLS);
            const int gy = y_org + (int)yy;
            const int gx = x_org + (int)xx;
            const bool ok = in & ((unsigned)gy < IMG_H) & ((unsigned)gx < IMG_W);
            live[j] = in;
            soff[j] = (int)(yy * SPITCH + xx);
            vc0[j] = 0.f; vc1[j] = 0.f; vc2[j] = 0.f;
            if (ok) {
                const float* p = img + (size_t)gy * IMG_W + gx;
                vc0[j] = __ldg(p);
                vc1[j] = __ldg(p + PLANE);
                vc2[j] = __ldg(p + 2 * PLANE);
            }
        }
#pragma unroll
        for (int j = 0; j < 3; j++) {
            if (live[j]) {
                *((float2*)&tileAB[0][0] + soff[j]) = make_float2(vc0[j], vc1[j]);
                *((float*)&tileC[0][0] + soff[j])   = vc2[j];
            }
        }
    }
    __syncthreads();

    // ---- compute: warp = 32 contiguous output px; 2 rows per thread ----
    const int lane = tid & 31;
    const int wrp  = tid >> 5;   // 0..7

    const int ox  = tx_tile * TILE_OX + lane;
    const int oy0 = ty_tile * TILE_OY + wrp * 2;

    const float u  = (float)ox  * (1.0f / OUT_W);
    const float vb = (float)oy0 * (1.0f / OUT_H);

    // tile-local source coords; origin folded in once
    float sx = fmaf(vb, ey_x, fmaf(u, ex_x, p1x)) - (float)x_org;
    float sy = fmaf(vb, ey_y, fmaf(u, ex_y, p1y)) - (float)y_org;
    const float dvx = ey_x * (1.0f / OUT_H);
    const float dvy = ey_y * (1.0f / OUT_H);

    const float2* __restrict__ tAB = &tileAB[0][0];
    const float*  __restrict__ tC  = &tileC[0][0];

    float* ob = out + (((size_t)g * CHANS) * OUT_H + oy0) * OUT_W + ox;

#pragma unroll
    for (int r = 0; r < 2; r++) {
        const float x0f = floorf(sx);
        const float y0f = floorf(sy);
        const float dx = sx - x0f;
        const float dy = sy - y0f;

        int idx = (int)y0f * SPITCH + (int)x0f;
        idx = min(max(idx, 0), IDX_LIM);   // memory safety only; never binds in-spec

        const float omdx = 1.0f - dx;
        const float omdy = 1.0f - dy;
        const float w00 = omdx * omdy;
        const float w10 = dx * omdy;
        const float w01 = omdx * dy;
        const float w11 = dx * dy;

        const float2 t00 = tAB[idx];
        const float2 t10 = tAB[idx + 1];
        const float2 t01 = tAB[idx + SPITCH];
        const float2 t11 = tAB[idx + SPITCH + 1];
        const float  c00 = tC[idx];
        const float  c10 = tC[idx + 1];
        const float  c01 = tC[idx + SPITCH];
        const float  c11 = tC[idx + SPITCH + 1];

        const float r0 = fmaf(t11.x, w11, fmaf(t01.x, w01, fmaf(t10.x, w10, t00.x * w00)));
        const float r1 = fmaf(t11.y, w11, fmaf(t01.y, w01, fmaf(t10.y, w10, t00.y * w00)));
        const float r2 = fmaf(c11,   w11, fmaf(c01,   w01, fmaf(c10,   w10, c00   * w00)));

        ob[0]          = r0;
        ob[OPLANE]     = r1;
        ob[2 * OPLANE] = r2;

        sx += dvx;
        sy += dvy;
        ob += OUT_W;
    }
}

extern "C" void kernel_launch(void* const* d_in, const int* in_sizes, int n_in,
                              void* d_out, int out_size) {
    const float* x     = (const float*)d_in[0];
    const float* boxes = (const float*)d_in[1];
    float* out         = (float*)d_out;

    dim3 grid(N_BOXES_TOTAL * NTX * NTY);   // 15360
    dim3 block(NTHREADS);
    rotated_roi_crop_v7<<<grid, block>>>(x, boxes, out);
}

// round 8
// speedup vs baseline: 3.9721x; 1.2502x over previous
#include <cuda_runtime.h>

// Rotated ROI cropper v8:
//   x:     [8, 3, 1024, 1024] fp32
//   boxes: [8, 64, 5] fp32  (cx, cy, w, h, angle_deg)
//   out:   [512, 3, 48, 320] fp32
//
// Kernel 1: per-box affine params (p1, ex, ey) -> __device__ global.
// Kernel 2: block = one 32x16 output tile (256 thr, 2 rows/thread).
//   Source window of a 32x16 tile spans <= 34.6 px/side; with tap, guard and
//   4-px left alignment it fits 38 rows x 44 cols. Staged via float4 LDG.128
//   (3 channels) -> split smem planes (float2 c0c1 + float c2). Taps are
//   4x LDS.64 + 4x LDS.32 per pixel; guard border removes per-pixel clamps;
//   one flat-index clamp keeps memory safety.

#define IMG_H 1024
#define IMG_W 1024
#define OUT_H 48
#define OUT_W 320
#define CHANS 3
#define N_BOXES_TOTAL 512
#define PLANE (IMG_H * IMG_W)
#define OPLANE (OUT_H * OUT_W)

#define TILE_OX 32
#define TILE_OY 16
#define NTX (OUT_W / TILE_OX)   // 10
#define NTY (OUT_H / TILE_OY)   // 3

#define SROWS 38
#define SCOLS 44                 // 11 float4 per row
#define F4PR  (SCOLS / 4)        // 11
#define IDX_LIM ((SROWS - 2) * SCOLS + (SCOLS - 2))

#define NTHREADS 256

__device__ float g_bp[N_BOXES_TOTAL * 8];   // p1x,p1y,exx,exy,eyx,eyy,pad,pad

__global__ void box_params_kernel(const float* __restrict__ boxes) {
    const int g = blockIdx.x * blockDim.x + threadIdx.x;
    if (g >= N_BOXES_TOTAL) return;
    const float* bp = boxes + g * 5;
    const float cx  = bp[0];
    const float cy  = bp[1];
    const float bw  = bp[2];
    const float bh  = bp[3];
    const float ang = bp[4];

    const float theta = -ang * 0.017453292519943295f;
    float s_, c_;
    sincosf(theta, &s_, &c_);
    const float b = c_ * 0.5f;
    const float a = s_ * 0.5f;

    const float p0x = cx - a * bh - b * bw;
    const float p0y = cy + b * bh - a * bw;
    const float p1x = cx + a * bh - b * bw;
    const float p1y = cy - b * bh - a * bw;
    const float p2x = 2.0f * cx - p0x;
    const float p2y = 2.0f * cy - p0y;

    float* o = g_bp + g * 8;
    o[0] = p1x;          o[1] = p1y;
    o[2] = p2x - p1x;    o[3] = p2y - p1y;   // ex
    o[4] = p0x - p1x;    o[5] = p0y - p1y;   // ey
}

__global__ __launch_bounds__(NTHREADS, 8)
void rotated_roi_crop_v8(const float* __restrict__ x,
                         float* __restrict__ out) {
    __shared__ float2 tileAB[SROWS][SCOLS];  // (c0, c1)
    __shared__ float  tileC [SROWS][SCOLS];  // c2

    const int bid     = blockIdx.x;
    const int tx_tile = bid % NTX;
    const int ty_tile = (bid / NTX) % NTY;
    const int g       = bid / (NTX * NTY);

    // ---- precomputed box params (broadcast) ----
    const float4 lo = __ldg((const float4*)(g_bp + g * 8));
    const float2 hi = __ldg((const float2*)(g_bp + g * 8 + 4));
    const float p1x = lo.x, p1y = lo.y;
    const float ex_x = lo.z, ex_y = lo.w;
    const float ey_x = hi.x, ey_y = hi.y;

    // ---- source bbox of this output tile (4 affine corners) ----
    const float u0 = (float)(tx_tile * TILE_OX)               * (1.0f / OUT_W);
    const float u1 = (float)(tx_tile * TILE_OX + TILE_OX - 1) * (1.0f / OUT_W);
    const float v0 = (float)(ty_tile * TILE_OY)               * (1.0f / OUT_H);
    const float v1 = (float)(ty_tile * TILE_OY + TILE_OY - 1) * (1.0f / OUT_H);

    const float sxa = p1x + u0 * ex_x + v0 * ey_x;
    const float sxb = p1x + u1 * ex_x + v0 * ey_x;
    const float sxc = p1x + u0 * ex_x + v1 * ey_x;
    const float sxd = p1x + u1 * ex_x + v1 * ey_x;
    const float sya = p1y + u0 * ex_y + v0 * ey_y;
    const float syb = p1y + u1 * ex_y + v0 * ey_y;
    const float syc = p1y + u0 * ex_y + v1 * ey_y;
    const float syd = p1y + u1 * ex_y + v1 * ey_y;

    const int fmin_x = (int)floorf(fminf(fminf(sxa, sxb), fminf(sxc, sxd)));
    const int fmin_y = (int)floorf(fminf(fminf(sya, syb), fminf(syc, syd)));
    const int fmax_y = (int)floorf(fmaxf(fmaxf(sya, syb), fmaxf(syc, syd)));

    const int x_org = fmin_x - 1;                   // 1-px guard
    const int x_al  = x_org - (x_org & 3);          // floor-align to 4 px (16B)
    const int y_org = fmin_y - 1;
    const int bhei  = min(fmax_y - fmin_y + 3, SROWS);

    // ---- staging: bhei rows x 11 float4-cells, 3 channels each ----
    const int batch = g >> 6;
    const float* img = x + (size_t)batch * CHANS * PLANE;
    const int tid = threadIdx.x;
    const int nf4 = F4PR * bhei;                    // <= 418

#pragma unroll
    for (int half = 0; half < 2; half++) {
        const int i = tid + half * NTHREADS;
        if (i < nf4) {
            const int yy  = i / F4PR;
            const int xx4 = i - yy * F4PR;
            const int gy  = y_org + yy;
            const int gxb = x_al + xx4 * 4;
            // all-or-nothing validity per float4 (gxb is 4-aligned)
            const bool ok = ((unsigned)gy < IMG_H) & ((unsigned)gxb <= (IMG_W - 4));
            float4 c0 = make_float4(0.f, 0.f, 0.f, 0.f);
            float4 c1 = c0, c2 = c0;
            if (ok) {
                const float* p = img + (size_t)gy * IMG_W + gxb;
                c0 = __ldg((const float4*)p);
                c1 = __ldg((const float4*)(p + PLANE));
                c2 = __ldg((const float4*)(p + 2 * PLANE));
            }
            float2* dAB = &tileAB[yy][xx4 * 4];
            dAB[0] = make_float2(c0.x, c1.x);
            dAB[1] = make_float2(c0.y, c1.y);
            dAB[2] = make_float2(c0.z, c1.z);
            dAB[3] = make_float2(c0.w, c1.w);
            *(float4*)&tileC[yy][xx4 * 4] = c2;
        }
    }
    __syncthreads();

    // ---- compute: warp = 32 contiguous output px; 2 rows per thread ----
    const int lane = tid & 31;
    const int wrp  = tid >> 5;   // 0..7

    const int ox  = tx_tile * TILE_OX + lane;
    const int oy0 = ty_tile * TILE_OY + wrp * 2;

    const float u  = (float)ox  * (1.0f / OUT_W);
    const float vb = (float)oy0 * (1.0f / OUT_H);

    float sx = fmaf(vb, ey_x, fmaf(u, ex_x, p1x)) - (float)x_al;
    float sy = fmaf(vb, ey_y, fmaf(u, ex_y, p1y)) - (float)y_org;
    const float dvx = ey_x * (1.0f / OUT_H);
    const float dvy = ey_y * (1.0f / OUT_H);

    const float2* __restrict__ tAB = &tileAB[0][0];
    const float*  __restrict__ tC  = &tileC[0][0];

    float* ob = out + (((size_t)g * CHANS) * OUT_H + oy0) * OUT_W + ox;

#pragma unroll
    for (int r = 0; r < 2; r++) {
        const float x0f = floorf(sx);
        const float y0f = floorf(sy);
        const float dx = sx - x0f;
        const float dy = sy - y0f;

        int idx = (int)y0f * SCOLS + (int)x0f;
        idx = min(max(idx, 0), IDX_LIM);   // memory safety; never binds in-spec

        const float omdx = 1.0f - dx;
        const float omdy = 1.0f - dy;
        const float w00 = omdx * omdy;
        const float w10 = dx * omdy;
        const float w01 = omdx * dy;
        const float w11 = dx * dy;

        const float2 t00 = tAB[idx];
        const float2 t10 = tAB[idx + 1];
        const float2 t01 = tAB[idx + SCOLS];
        const float2 t11 = tAB[idx + SCOLS + 1];
        const float  c00 = tC[idx];
        const float  c10 = tC[idx + 1];
        const float  c01 = tC[idx + SCOLS];
        const float  c11 = tC[idx + SCOLS + 1];

        const float r0 = fmaf(t11.x, w11, fmaf(t01.x, w01, fmaf(t10.x, w10, t00.x * w00)));
        const float r1 = fmaf(t11.y, w11, fmaf(t01.y, w01, fmaf(t10.y, w10, t00.y * w00)));
        const float r2 = fmaf(c11,   w11, fmaf(c01,   w01, fmaf(c10,   w10, c00   * w00)));

        ob[0]          = r0;
        ob[OPLANE]     = r1;
        ob[2 * OPLANE] = r2;

        sx += dvx;
        sy += dvy;
        ob += OUT_W;
    }
}

extern "C" void kernel_launch(void* const* d_in, const int* in_sizes, int n_in,
                              void* d_out, int out_size) {
    const float* x     = (const float*)d_in[0];
    const float* boxes = (const float*)d_in[1];
    float* out         = (float*)d_out;

    box_params_kernel<<<2, 256>>>(boxes);
    rotated_roi_crop_v8<<<N_BOXES_TOTAL * NTX * NTY, NTHREADS>>>(x, out);
}

// round 10
// speedup vs baseline: 4.4797x; 1.1278x over previous
#include <cuda_runtime.h>
#include <cuda_fp16.h>
#include <cstdint>

// Rotated ROI cropper v9b: fp16-packed smem texels (c0,c1,c2,0 in 8B).
//   x:     [8, 3, 1024, 1024] fp32
//   boxes: [8, 64, 5] fp32  (cx, cy, w, h, angle_deg)
//   out:   [512, 3, 48, 320] fp32
//
// Kernel 1: per-box affine params (p1, ex, ey) -> __device__ global.
// Kernel 2: block = one 32x16 output tile (256 thr, 2 rows/thread).
//   38x44 source window (bw<=300, bh<=60, |ang|<=45: tile span <= 34.6 px
//   + tap + guard + 4-px alignment). Staged via 3x LDG.128 per 4-col cell,
//   converted to half and written as 2x STS.128 (contiguous). Each bilinear
//   tap is ONE LDS.64 carrying all 3 channels; weights/accum stay fp32.

#define IMG_H 1024
#define IMG_W 1024
#define OUT_H 48
#define OUT_W 320
#define CHANS 3
#define N_BOXES_TOTAL 512
#define PLANE (IMG_H * IMG_W)
#define OPLANE (OUT_H * OUT_W)

#define TILE_OX 32
#define TILE_OY 16
#define NTX (OUT_W / TILE_OX)   // 10
#define NTY (OUT_H / TILE_OY)   // 3

#define SROWS 38
#define SCOLS 44                 // 11 float4-cells per row
#define F4PR  (SCOLS / 4)        // 11
#define IDX_LIM ((SROWS - 2) * SCOLS + (SCOLS - 2))

#define NTHREADS 256

__device__ __forceinline__ uint32_t h2_to_u32(__half2 h) {
    uint32_t u;
    *reinterpret_cast<__half2*>(&u) = h;
    return u;
}
__device__ __forceinline__ __half2 u32_to_h2(uint32_t u) {
    return *reinterpret_cast<__half2*>(&u);
}

__device__ float g_bp[N_BOXES_TOTAL * 8];   // p1x,p1y,exx,exy,eyx,eyy,pad,pad

__global__ void box_params_kernel(const float* __restrict__ boxes) {
    const int g = blockIdx.x * blockDim.x + threadIdx.x;
    if (g >= N_BOXES_TOTAL) return;
    const float* bp = boxes + g * 5;
    const float cx  = bp[0];
    const float cy  = bp[1];
    const float bw  = bp[2];
    const float bh  = bp[3];
    const float ang = bp[4];

    const float theta = -ang * 0.017453292519943295f;
    float s_, c_;
    sincosf(theta, &s_, &c_);
    const float b = c_ * 0.5f;
    const float a = s_ * 0.5f;

    const float p0x = cx - a * bh - b * bw;
    const float p0y = cy + b * bh - a * bw;
    const float p1x = cx + a * bh - b * bw;
    const float p1y = cy - b * bh - a * bw;
    const float p2x = 2.0f * cx - p0x;
    const float p2y = 2.0f * cy - p0y;

    float* o = g_bp + g * 8;
    o[0] = p1x;          o[1] = p1y;
    o[2] = p2x - p1x;    o[3] = p2y - p1y;   // ex
    o[4] = p0x - p1x;    o[5] = p0y - p1y;   // ey
}

__global__ __launch_bounds__(NTHREADS, 8)
void rotated_roi_crop_v9(const float* __restrict__ x,
                         float* __restrict__ out) {
    // Each texel: uint2 = { half2(c0,c1), half2(c2,0) } = 8 bytes.
    __shared__ __align__(16) uint2 tileH[SROWS][SCOLS];

    const int bid     = blockIdx.x;
    const int tx_tile = bid % NTX;
    const int ty_tile = (bid / NTX) % NTY;
    const int g       = bid / (NTX * NTY);

    // ---- precomputed box params (broadcast) ----
    const float4 lo = __ldg((const float4*)(g_bp + g * 8));
    const float2 hi = __ldg((const float2*)(g_bp + g * 8 + 4));
    const float p1x = lo.x, p1y = lo.y;
    const float ex_x = lo.z, ex_y = lo.w;
    const float ey_x = hi.x, ey_y = hi.y;

    // ---- source bbox of this output tile (4 affine corners) ----
    const float u0 = (float)(tx_tile * TILE_OX)               * (1.0f / OUT_W);
    const float u1 = (float)(tx_tile * TILE_OX + TILE_OX - 1) * (1.0f / OUT_W);
    const float v0 = (float)(ty_tile * TILE_OY)               * (1.0f / OUT_H);
    const float v1 = (float)(ty_tile * TILE_OY + TILE_OY - 1) * (1.0f / OUT_H);

    const float sxa = p1x + u0 * ex_x + v0 * ey_x;
    const float sxb = p1x + u1 * ex_x + v0 * ey_x;
    const float sxc = p1x + u0 * ex_x + v1 * ey_x;
    const float sxd = p1x + u1 * ex_x + v1 * ey_x;
    const float sya = p1y + u0 * ex_y + v0 * ey_y;
    const float syb = p1y + u1 * ex_y + v0 * ey_y;
    const float syc = p1y + u0 * ex_y + v1 * ey_y;
    const float syd = p1y + u1 * ex_y + v1 * ey_y;

    const int fmin_x = (int)floorf(fminf(fminf(sxa, sxb), fminf(sxc, sxd)));
    const int fmin_y = (int)floorf(fminf(fminf(sya, syb), fminf(syc, syd)));
    const int fmax_y = (int)floorf(fmaxf(fmaxf(sya, syb), fmaxf(syc, syd)));

    const int x_org = fmin_x - 1;                   // 1-px guard
    const int x_al  = x_org - (x_org & 3);          // floor-align to 4 px (16B)
    const int y_org = fmin_y - 1;
    const int bhei  = min(fmax_y - fmin_y + 3, SROWS);

    // ---- staging: bhei rows x 11 float4-cells; fp16 pack; 2x STS.128/cell ----
    const int batch = g >> 6;
    const float* img = x + (size_t)batch * CHANS * PLANE;
    const int tid = threadIdx.x;
    const int nf4 = F4PR * bhei;                    // <= 418

#pragma unroll
    for (int half_ = 0; half_ < 2; half_++) {
        const int i = tid + half_ * NTHREADS;
        if (i < nf4) {
            const int yy  = i / F4PR;
            const int xx4 = i - yy * F4PR;
            const int gy  = y_org + yy;
            const int gxb = x_al + xx4 * 4;
            const bool ok = ((unsigned)gy < IMG_H) & ((unsigned)gxb <= (IMG_W - 4));
            float4 c0 = make_float4(0.f, 0.f, 0.f, 0.f);
            float4 c1 = c0, c2 = c0;
            if (ok) {
                const float* p = img + (size_t)gy * IMG_W + gxb;
                c0 = __ldg((const float4*)p);
                c1 = __ldg((const float4*)(p + PLANE));
                c2 = __ldg((const float4*)(p + 2 * PLANE));
            }
            uint4 w0, w1;
            w0.x = h2_to_u32(__floats2half2_rn(c0.x, c1.x));
            w0.y = h2_to_u32(__floats2half2_rn(c2.x, 0.f));
            w0.z = h2_to_u32(__floats2half2_rn(c0.y, c1.y));
            w0.w = h2_to_u32(__floats2half2_rn(c2.y, 0.f));
            w1.x = h2_to_u32(__floats2half2_rn(c0.z, c1.z));
            w1.y = h2_to_u32(__floats2half2_rn(c2.z, 0.f));
            w1.z = h2_to_u32(__floats2half2_rn(c0.w, c1.w));
            w1.w = h2_to_u32(__floats2half2_rn(c2.w, 0.f));
            uint4* d = (uint4*)&tileH[yy][xx4 * 4];
            d[0] = w0;
            d[1] = w1;
        }
    }
    __syncthreads();

    // ---- compute: warp = 32 contiguous output px; 2 rows per thread ----
    const int lane = tid & 31;
    const int wrp  = tid >> 5;   // 0..7

    const int ox  = tx_tile * TILE_OX + lane;
    const int oy0 = ty_tile * TILE_OY + wrp * 2;

    const float u  = (float)ox  * (1.0f / OUT_W);
    const float vb = (float)oy0 * (1.0f / OUT_H);

    float sx = fmaf(vb, ey_x, fmaf(u, ex_x, p1x)) - (float)x_al;
    float sy = fmaf(vb, ey_y, fmaf(u, ex_y, p1y)) - (float)y_org;
    const float dvx = ey_x * (1.0f / OUT_H);
    const float dvy = ey_y * (1.0f / OUT_H);

    const uint2* __restrict__ tH = &tileH[0][0];

    float* ob = out + (((size_t)g * CHANS) * OUT_H + oy0) * OUT_W + ox;

#pragma unroll
    for (int r = 0; r < 2; r++) {
        const float x0f = floorf(sx);
        const float y0f = floorf(sy);
        const float dx = sx - x0f;
        const float dy = sy - y0f;

        int idx = (int)y0f * SCOLS + (int)x0f;
        idx = min(max(idx, 0), IDX_LIM);   // memory safety; never binds in-spec

        const float omdx = 1.0f - dx;
        const float omdy = 1.0f - dy;
        const float w00 = omdx * omdy;
        const float w10 = dx * omdy;
        const float w01 = omdx * dy;
        const float w11 = dx * dy;

        const uint2 t00 = tH[idx];
        const uint2 t10 = tH[idx + 1];
        const uint2 t01 = tH[idx + SCOLS];
        const uint2 t11 = tH[idx + SCOLS + 1];

        const float2 ab00 = __half22float2(u32_to_h2(t00.x));
        const float2 ab10 = __half22float2(u32_to_h2(t10.x));
        const float2 ab01 = __half22float2(u32_to_h2(t01.x));
        const float2 ab11 = __half22float2(u32_to_h2(t11.x));
        const float  c00v = __low2float(u32_to_h2(t00.y));
        const float  c10v = __low2float(u32_to_h2(t10.y));
        const float  c01v = __low2float(u32_to_h2(t01.y));
        const float  c11v = __low2float(u32_to_h2(t11.y));

        const float r0 = fmaf(ab11.x, w11, fmaf(ab01.x, w01, fmaf(ab10.x, w10, ab00.x * w00)));
        const float r1 = fmaf(ab11.y, w11, fmaf(ab01.y, w01, fmaf(ab10.y, w10, ab00.y * w00)));
        const float r2 = fmaf(c11v,   w11, fmaf(c01v,   w01, fmaf(c10v,   w10, c00v   * w00)));

        ob[0]          = r0;
        ob[OPLANE]     = r1;
        ob[2 * OPLANE] = r2;

        sx += dvx;
        sy += dvy;
        ob += OUT_W;
    }
}

extern "C" void kernel_launch(void* const* d_in, const int* in_sizes, int n_in,
                              void* d_out, int out_size) {
    const float* x     = (const float*)d_in[0];
    const float* boxes = (const float*)d_in[1];
    float* out         = (float*)d_out;

    box_params_kernel<<<2, 256>>>(boxes);
    rotated_roi_crop_v9<<<N_BOXES_TOTAL * NTX * NTY, NTHREADS>>>(x, out);
}

// round 11
// speedup vs baseline: 4.5496x; 1.0156x over previous
#include <cuda_runtime.h>
#include <cuda_fp16.h>
#include <cstdint>

// Rotated ROI cropper v10: fp16 texels + variable-width staging.
//   x:     [8, 3, 1024, 1024] fp32
//   boxes: [8, 64, 5] fp32  (cx, cy, w, h, angle_deg)
//   out:   [512, 3, 48, 320] fp32
//
// Kernel 1: per-box affine params (p1, ex, ey).
// Kernel 2: block = one 32x16 output tile (256 thr, 2 rows/thread).
//   Source window trimmed per-tile in BOTH dims (rows bhei<=38, cols
//   nf4row<=11 float4-cells). Staged via 3x LDG.128/cell -> fp16 texel
//   (c0,c1,c2,0 in 8B) -> 2x STS.128. Tap = ONE LDS.64 for all 3 channels;
//   weights/accumulation fp32.

#define IMG_H 1024
#define IMG_W 1024
#define OUT_H 48
#define OUT_W 320
#define CHANS 3
#define N_BOXES_TOTAL 512
#define PLANE (IMG_H * IMG_W)
#define OPLANE (OUT_H * OUT_W)

#define TILE_OX 32
#define TILE_OY 16
#define NTX (OUT_W / TILE_OX)   // 10
#define NTY (OUT_H / TILE_OY)   // 3

#define SROWS 38
#define SCOLS 46                 // texel pitch; 368B/row (16B-aligned, not 128B-multiple)
#define IDX_LIM ((SROWS - 2) * SCOLS + (SCOLS - 2))

#define NTHREADS 256

__device__ __forceinline__ uint32_t h2_to_u32(__half2 h) {
    uint32_t u;
    *reinterpret_cast<__half2*>(&u) = h;
    return u;
}
__device__ __forceinline__ __half2 u32_to_h2(uint32_t u) {
    return *reinterpret_cast<__half2*>(&u);
}

__device__ float g_bp[N_BOXES_TOTAL * 8];   // p1x,p1y,exx,exy,eyx,eyy,pad,pad

__global__ void box_params_kernel(const float* __restrict__ boxes) {
    const int g = blockIdx.x * blockDim.x + threadIdx.x;
    if (g >= N_BOXES_TOTAL) return;
    const float* bp = boxes + g * 5;
    const float cx  = bp[0];
    const float cy  = bp[1];
    const float bw  = bp[2];
    const float bh  = bp[3];
    const float ang = bp[4];

    const float theta = -ang * 0.017453292519943295f;
    float s_, c_;
    sincosf(theta, &s_, &c_);
    const float b = c_ * 0.5f;
    const float a = s_ * 0.5f;

    const float p0x = cx - a * bh - b * bw;
    const float p0y = cy + b * bh - a * bw;
    const float p1x = cx + a * bh - b * bw;
    const float p1y = cy - b * bh - a * bw;
    const float p2x = 2.0f * cx - p0x;
    const float p2y = 2.0f * cy - p0y;

    float* o = g_bp + g * 8;
    o[0] = p1x;          o[1] = p1y;
    o[2] = p2x - p1x;    o[3] = p2y - p1y;   // ex
    o[4] = p0x - p1x;    o[5] = p0y - p1y;   // ey
}

__global__ __launch_bounds__(NTHREADS, 8)
void rotated_roi_crop_v10(const float* __restrict__ x,
                          float* __restrict__ out) {
    // Each texel: uint2 = { half2(c0,c1), half2(c2,0) } = 8 bytes.
    __shared__ __align__(16) uint2 tileH[SROWS][SCOLS];

    const int bid     = blockIdx.x;
    const int tx_tile = bid % NTX;
    const int ty_tile = (bid / NTX) % NTY;
    const int g       = bid / (NTX * NTY);

    // ---- precomputed box params (broadcast) ----
    const float4 lo = __ldg((const float4*)(g_bp + g * 8));
    const float2 hi = __ldg((const float2*)(g_bp + g * 8 + 4));
    const float p1x = lo.x, p1y = lo.y;
    const float ex_x = lo.z, ex_y = lo.w;
    const float ey_x = hi.x, ey_y = hi.y;

    // ---- source bbox of this output tile (4 affine corners) ----
    const float u0 = (float)(tx_tile * TILE_OX)               * (1.0f / OUT_W);
    const float u1 = (float)(tx_tile * TILE_OX + TILE_OX - 1) * (1.0f / OUT_W);
    const float v0 = (float)(ty_tile * TILE_OY)               * (1.0f / OUT_H);
    const float v1 = (float)(ty_tile * TILE_OY + TILE_OY - 1) * (1.0f / OUT_H);

    const float sxa = p1x + u0 * ex_x + v0 * ey_x;
    const float sxb = p1x + u1 * ex_x + v0 * ey_x;
    const float sxc = p1x + u0 * ex_x + v1 * ey_x;
    const float sxd = p1x + u1 * ex_x + v1 * ey_x;
    const float sya = p1y + u0 * ex_y + v0 * ey_y;
    const float syb = p1y + u1 * ex_y + v0 * ey_y;
    const float syc = p1y + u0 * ex_y + v1 * ey_y;
    const float syd = p1y + u1 * ex_y + v1 * ey_y;

    const int fmin_x = (int)floorf(fminf(fminf(sxa, sxb), fminf(sxc, sxd)));
    const int fmax_x = (int)floorf(fmaxf(fmaxf(sxa, sxb), fmaxf(sxc, sxd)));
    const int fmin_y = (int)floorf(fminf(fminf(sya, syb), fminf(syc, syd)));
    const int fmax_y = (int)floorf(fmaxf(fmaxf(sya, syb), fmaxf(syc, syd)));

    const int x_org = fmin_x - 1;                   // 1-px guard
    const int x_al  = x_org - (x_org & 3);          // floor-align to 4 px (16B)
    const int y_org = fmin_y - 1;
    const int bhei  = min(fmax_y - fmin_y + 3, SROWS);
    // cols needed: x_al .. fmax_x+2 inclusive
    const int nf4row = min((fmax_x + 2 - x_al + 4) >> 2, SCOLS / 4);  // <= 11
    const float inv_nf4 = 1.0f / (float)nf4row;

    // ---- staging: bhei rows x nf4row float4-cells; fp16 pack; 2x STS.128 ----
    const int batch = g >> 6;
    const float* img = x + (size_t)batch * CHANS * PLANE;
    const int tid = threadIdx.x;
    const int nf4 = nf4row * bhei;                  // <= 418

#pragma unroll
    for (int half_ = 0; half_ < 2; half_++) {
        const int i = tid + half_ * NTHREADS;
        if (i < nf4) {
            // exact for i<512, nf4row<=11
            const int yy  = (int)(((float)i + 0.5f) * inv_nf4);
            const int xx4 = i - yy * nf4row;
            const int gy  = y_org + yy;
            const int gxb = x_al + xx4 * 4;
            const bool ok = ((unsigned)gy < IMG_H) & ((unsigned)gxb <= (IMG_W - 4));
            float4 c0 = make_float4(0.f, 0.f, 0.f, 0.f);
            float4 c1 = c0, c2 = c0;
            if (ok) {
                const float* p = img + (size_t)gy * IMG_W + gxb;
                c0 = __ldg((const float4*)p);
                c1 = __ldg((const float4*)(p + PLANE));
                c2 = __ldg((const float4*)(p + 2 * PLANE));
            }
            uint4 w0, w1;
            w0.x = h2_to_u32(__floats2half2_rn(c0.x, c1.x));
            w0.y = h2_to_u32(__floats2half2_rn(c2.x, 0.f));
            w0.z = h2_to_u32(__floats2half2_rn(c0.y, c1.y));
            w0.w = h2_to_u32(__floats2half2_rn(c2.y, 0.f));
            w1.x = h2_to_u32(__floats2half2_rn(c0.z, c1.z));
            w1.y = h2_to_u32(__floats2half2_rn(c2.z, 0.f));
            w1.z = h2_to_u32(__floats2half2_rn(c0.w, c1.w));
            w1.w = h2_to_u32(__floats2half2_rn(c2.w, 0.f));
            uint4* d = (uint4*)&tileH[yy][xx4 * 4];
            d[0] = w0;
            d[1] = w1;
        }
    }
    __syncthreads();

    // ---- compute: warp = 32 contiguous output px; 2 rows per thread ----
    const int lane = tid & 31;
    const int wrp  = tid >> 5;   // 0..7

    const int ox  = tx_tile * TILE_OX + lane;
    const int oy0 = ty_tile * TILE_OY + wrp * 2;

    const float u  = (float)ox  * (1.0f / OUT_W);
    const float vb = (float)oy0 * (1.0f / OUT_H);

    float sx = fmaf(vb, ey_x, fmaf(u, ex_x, p1x)) - (float)x_al;
    float sy = fmaf(vb, ey_y, fmaf(u, ex_y, p1y)) - (float)y_org;
    const float dvx = ey_x * (1.0f / OUT_H);
    const float dvy = ey_y * (1.0f / OUT_H);

    const uint2* __restrict__ tH = &tileH[0][0];

    float* ob = out + (((size_t)g * CHANS) * OUT_H + oy0) * OUT_W + ox;

#pragma unroll
    for (int r = 0; r < 2; r++) {
        const float x0f = floorf(sx);
        const float y0f = floorf(sy);
        const float dx = sx - x0f;
        const float dy = sy - y0f;

        int idx = (int)y0f * SCOLS + (int)x0f;
        idx = min(max(idx, 0), IDX_LIM);   // memory safety; never binds in-spec

        const float omdx = 1.0f - dx;
        const float omdy = 1.0f - dy;
        const float w00 = omdx * omdy;
        const float w10 = dx * omdy;
        const float w01 = omdx * dy;
        const float w11 = dx * dy;

        const uint2 t00 = tH[idx];
        const uint2 t10 = tH[idx + 1];
        const uint2 t01 = tH[idx + SCOLS];
        const uint2 t11 = tH[idx + SCOLS + 1];

        const float2 ab00 = __half22float2(u32_to_h2(t00.x));
        const float2 ab10 = __half22float2(u32_to_h2(t10.x));
        const float2 ab01 = __half22float2(u32_to_h2(t01.x));
        const float2 ab11 = __half22float2(u32_to_h2(t11.x));
        const float  c00v = __low2float(u32_to_h2(t00.y));
        const float  c10v = __low2float(u32_to_h2(t10.y));
        const float  c01v = __low2float(u32_to_h2(t01.y));
        const float  c11v = __low2float(u32_to_h2(t11.y));

        const float r0 = fmaf(ab11.x, w11, fmaf(ab01.x, w01, fmaf(ab10.x, w10, ab00.x * w00)));
        const float r1 = fmaf(ab11.y, w11, fmaf(ab01.y, w01, fmaf(ab10.y, w10, ab00.y * w00)));
        const float r2 = fmaf(c11v,   w11, fmaf(c01v,   w01, fmaf(c10v,   w10, c00v   * w00)));

        ob[0]          = r0;
        ob[OPLANE]     = r1;
        ob[2 * OPLANE] = r2;

        sx += dvx;
        sy += dvy;
        ob += OUT_W;
    }
}

extern "C" void kernel_launch(void* const* d_in, const int* in_sizes, int n_in,
                              void* d_out, int out_size) {
    const float* x     = (const float*)d_in[0];
    const float* boxes = (const float*)d_in[1];
    float* out         = (float*)d_out;

    box_params_kernel<<<2, 256>>>(boxes);
    rotated_roi_crop_v10<<<N_BOXES_TOTAL * NTX * NTY, NTHREADS>>>(x, out);
}

// round 12
// speedup vs baseline: 4.7204x; 1.0375x over previous
#include <cuda_runtime.h>
#include <cuda_fp16.h>
#include <cstdint>

// Rotated ROI cropper v11: single fused kernel (v10 + inline box params).
//   x:     [8, 3, 1024, 1024] fp32
//   boxes: [8, 64, 5] fp32  (cx, cy, w, h, angle_deg)
//   out:   [512, 3, 48, 320] fp32
//
// Block = one 32x16 output tile (256 thr, 2 rows/thread).
// Source window trimmed per-tile in BOTH dims (rows bhei<=38, cols
// nf4row<=11 float4-cells). Staged via 3x LDG.128/cell -> fp16 texel
// (c0,c1,c2,0 in 8B) -> 2x STS.128. Tap = ONE LDS.64 for all 3 channels;
// weights/accumulation fp32.

#define IMG_H 1024
#define IMG_W 1024
#define OUT_H 48
#define OUT_W 320
#define CHANS 3
#define N_BOXES_TOTAL 512
#define PLANE (IMG_H * IMG_W)
#define OPLANE (OUT_H * OUT_W)

#define TILE_OX 32
#define TILE_OY 16
#define NTX (OUT_W / TILE_OX)   // 10
#define NTY (OUT_H / TILE_OY)   // 3

#define SROWS 38
#define SCOLS 46                 // texel pitch; 368B/row (16B-aligned, not 128B-multiple)
#define IDX_LIM ((SROWS - 2) * SCOLS + (SCOLS - 2))

#define NTHREADS 256

__device__ __forceinline__ uint32_t h2_to_u32(__half2 h) {
    uint32_t u;
    *reinterpret_cast<__half2*>(&u) = h;
    return u;
}
__device__ __forceinline__ __half2 u32_to_h2(uint32_t u) {
    return *reinterpret_cast<__half2*>(&u);
}

__global__ __launch_bounds__(NTHREADS, 8)
void rotated_roi_crop_v11(const float* __restrict__ x,
                          const float* __restrict__ boxes,
                          float* __restrict__ out) {
    // Each texel: uint2 = { half2(c0,c1), half2(c2,0) } = 8 bytes.
    __shared__ __align__(16) uint2 tileH[SROWS][SCOLS];

    const int bid     = blockIdx.x;
    const int tx_tile = bid % NTX;
    const int ty_tile = (bid / NTX) % NTY;
    const int g       = bid / (NTX * NTY);

    // ---- box params (uniform broadcast; ~30 ops incl. 2 MUFU) ----
    const float* bp = boxes + g * 5;
    const float cx  = bp[0];
    const float cy  = bp[1];
    const float bw  = bp[2];
    const float bh  = bp[3];
    const float ang = bp[4];

    const float theta = -ang * 0.017453292519943295f;
    float s_, c_;
    sincosf(theta, &s_, &c_);
    const float b = c_ * 0.5f;
    const float a = s_ * 0.5f;

    const float p1x = cx + a * bh - b * bw;
    const float p1y = cy - b * bh - a * bw;
    const float ex_x = 2.0f * (b * bw);            // p2x - p1x = 2(cx - p1x) - (p0x - p1x)... derived:
    // p0 - p1 = (-2a*bh, 2b*bh); p2 - p1 = 2(cx-p1x, cy-p1y) - (p0-p1)
    const float ey_x = -2.0f * a * bh;
    const float ey_y =  2.0f * b * bh;
    const float ex_x2 = 2.0f * (cx - p1x) - ey_x;  // = 2b*bw + 2a*bh - (-2a*bh)? use exact form
    const float ex_y2 = 2.0f * (cy - p1y) - ey_y;
    (void)ex_x;
    const float exx = ex_x2;
    const float exy = ex_y2;

    // ---- source bbox of this output tile (4 affine corners) ----
    const float u0 = (float)(tx_tile * TILE_OX)               * (1.0f / OUT_W);
    const float u1 = (float)(tx_tile * TILE_OX + TILE_OX - 1) * (1.0f / OUT_W);
    const float v0 = (float)(ty_tile * TILE_OY)               * (1.0f / OUT_H);
    const float v1 = (float)(ty_tile * TILE_OY + TILE_OY - 1) * (1.0f / OUT_H);

    const float sxa = p1x + u0 * exx + v0 * ey_x;
    const float sxb = p1x + u1 * exx + v0 * ey_x;
    const float sxc = p1x + u0 * exx + v1 * ey_x;
    const float sxd = p1x + u1 * exx + v1 * ey_x;
    const float sya = p1y + u0 * exy + v0 * ey_y;
    const float syb = p1y + u1 * exy + v0 * ey_y;
    const float syc = p1y + u0 * exy + v1 * ey_y;
    const float syd = p1y + u1 * exy + v1 * ey_y;

    const int fmin_x = (int)floorf(fminf(fminf(sxa, sxb), fminf(sxc, sxd)));
    const int fmax_x = (int)floorf(fmaxf(fmaxf(sxa, sxb), fmaxf(sxc, sxd)));
    const int fmin_y = (int)floorf(fminf(fminf(sya, syb), fminf(syc, syd)));
    const int fmax_y = (int)floorf(fmaxf(fmaxf(sya, syb), fmaxf(syc, syd)));

    const int x_org = fmin_x - 1;                   // 1-px guard
    const int x_al  = x_org - (x_org & 3);          // floor-align to 4 px (16B)
    const int y_org = fmin_y - 1;
    const int bhei  = min(fmax_y - fmin_y + 3, SROWS);
    // cols needed: x_al .. fmax_x+2 inclusive
    const int nf4row = min((fmax_x + 2 - x_al + 4) >> 2, SCOLS / 4);  // <= 11
    const float inv_nf4 = 1.0f / (float)nf4row;

    // ---- staging: bhei rows x nf4row float4-cells; fp16 pack; 2x STS.128 ----
    const int batch = g >> 6;
    const float* img = x + (size_t)batch * CHANS * PLANE;
    const int tid = threadIdx.x;
    const int nf4 = nf4row * bhei;                  // <= 418

#pragma unroll
    for (int half_ = 0; half_ < 2; half_++) {
        const int i = tid + half_ * NTHREADS;
        if (i < nf4) {
            // exact for i<512, nf4row<=11
            const int yy  = (int)(((float)i + 0.5f) * inv_nf4);
            const int xx4 = i - yy * nf4row;
            const int gy  = y_org + yy;
            const int gxb = x_al + xx4 * 4;
            const bool ok = ((unsigned)gy < IMG_H) & ((unsigned)gxb <= (IMG_W - 4));
            float4 c0 = make_float4(0.f, 0.f, 0.f, 0.f);
            float4 c1 = c0, c2 = c0;
            if (ok) {
                const float* p = img + (size_t)gy * IMG_W + gxb;
                c0 = __ldg((const float4*)p);
                c1 = __ldg((const float4*)(p + PLANE));
                c2 = __ldg((const float4*)(p + 2 * PLANE));
            }
            uint4 w0, w1;
            w0.x = h2_to_u32(__floats2half2_rn(c0.x, c1.x));
            w0.y = h2_to_u32(__floats2half2_rn(c2.x, 0.f));
            w0.z = h2_to_u32(__floats2half2_rn(c0.y, c1.y));
            w0.w = h2_to_u32(__floats2half2_rn(c2.y, 0.f));
            w1.x = h2_to_u32(__floats2half2_rn(c0.z, c1.z));
            w1.y = h2_to_u32(__floats2half2_rn(c2.z, 0.f));
            w1.z = h2_to_u32(__floats2half2_rn(c0.w, c1.w));
            w1.w = h2_to_u32(__floats2half2_rn(c2.w, 0.f));
            uint4* d = (uint4*)&tileH[yy][xx4 * 4];
            d[0] = w0;
            d[1] = w1;
        }
    }
    __syncthreads();

    // ---- compute: warp = 32 contiguous output px; 2 rows per thread ----
    const int lane = tid & 31;
    const int wrp  = tid >> 5;   // 0..7

    const int ox  = tx_tile * TILE_OX + lane;
    const int oy0 = ty_tile * TILE_OY + wrp * 2;

    const float u  = (float)ox  * (1.0f / OUT_W);
    const float vb = (float)oy0 * (1.0f / OUT_H);

    float sx = fmaf(vb, ey_x, fmaf(u, exx, p1x)) - (float)x_al;
    float sy = fmaf(vb, ey_y, fmaf(u, exy, p1y)) - (float)y_org;
    const float dvx = ey_x * (1.0f / OUT_H);
    const float dvy = ey_y * (1.0f / OUT_H);

    const uint2* __restrict__ tH = &tileH[0][0];

    float* ob = out + (((size_t)g * CHANS) * OUT_H + oy0) * OUT_W + ox;

#pragma unroll
    for (int r = 0; r < 2; r++) {
        const float x0f = floorf(sx);
        const float y0f = floorf(sy);
        const float dx = sx - x0f;
        const float dy = sy - y0f;

        int idx = (int)y0f * SCOLS + (int)x0f;
        idx = min(max(idx, 0), IDX_LIM);   // memory safety; never binds in-spec

        const float omdx = 1.0f - dx;
        const float omdy = 1.0f - dy;
        const float w00 = omdx * omdy;
        const float w10 = dx * omdy;
        const float w01 = omdx * dy;
        const float w11 = dx * dy;

        const uint2 t00 = tH[idx];
        const uint2 t10 = tH[idx + 1];
        const uint2 t01 = tH[idx + SCOLS];
        const uint2 t11 = tH[idx + SCOLS + 1];

        const float2 ab00 = __half22float2(u32_to_h2(t00.x));
        const float2 ab10 = __half22float2(u32_to_h2(t10.x));
        const float2 ab01 = __half22float2(u32_to_h2(t01.x));
        const float2 ab11 = __half22float2(u32_to_h2(t11.x));
        const float  c00v = __low2float(u32_to_h2(t00.y));
        const float  c10v = __low2float(u32_to_h2(t10.y));
        const float  c01v = __low2float(u32_to_h2(t01.y));
        const float  c11v = __low2float(u32_to_h2(t11.y));

        const float r0 = fmaf(ab11.x, w11, fmaf(ab01.x, w01, fmaf(ab10.x, w10, ab00.x * w00)));
        const float r1 = fmaf(ab11.y, w11, fmaf(ab01.y, w01, fmaf(ab10.y, w10, ab00.y * w00)));
        const float r2 = fmaf(c11v,   w11, fmaf(c01v,   w01, fmaf(c10v,   w10, c00v   * w00)));

        ob[0]          = r0;
        ob[OPLANE]     = r1;
        ob[2 * OPLANE] = r2;

        sx += dvx;
        sy += dvy;
        ob += OUT_W;
    }
}

extern "C" void kernel_launch(void* const* d_in, const int* in_sizes, int n_in,
                              void* d_out, int out_size) {
    const float* x     = (const float*)d_in[0];
    const float* boxes = (const float*)d_in[1];
    float* out         = (float*)d_out;

    rotated_roi_crop_v11<<<N_BOXES_TOTAL * NTX * NTY, NTHREADS>>>(x, boxes, out);
}